// round 1
// baseline (speedup 1.0000x reference)
#include <cuda_runtime.h>

#define N_AG 4096
#define M_CL 256
#define KD 32
#define SPLIT 8
#define CHUNK (N_AG / SPLIT)   /* 512 */
#define TILE 32
#define PSTRIDE 1064           /* 1024 S + 32 s + Z + cnt, padded (16B-mult) */
#define W_EPS 1e-6f

// static scratch (no allocations allowed)
__device__ float g_v[N_AG * KD];
__device__ float g_part[M_CL * SPLIT * PSTRIDE];

// ---------------------------------------------------------------------------
// Kernel A: batched 32x32 SPD solve, one warp per matrix, register Gauss-Jordan
// lane r holds row r of A (32 regs) + rhs. Pivot row normalized then broadcast
// via shfl. Fully unrolled so a[] stays in registers.
// ---------------------------------------------------------------------------
__global__ void __launch_bounds__(256) solve_kernel(const float* __restrict__ A,
                                                    const float* __restrict__ rhs) {
  int gw   = (blockIdx.x * blockDim.x + threadIdx.x) >> 5;
  int lane = threadIdx.x & 31;
  const float* Ar = A + (size_t)gw * (KD * KD) + lane * KD;

  float a[KD];
#pragma unroll
  for (int q = 0; q < KD / 4; q++) {
    float4 t4 = *reinterpret_cast<const float4*>(Ar + 4 * q);
    a[4 * q + 0] = t4.x; a[4 * q + 1] = t4.y;
    a[4 * q + 2] = t4.z; a[4 * q + 3] = t4.w;
  }
  float b = rhs[gw * KD + lane];

#pragma unroll
  for (int j = 0; j < KD; j++) {
    float pd  = __shfl_sync(0xffffffffu, a[j], j);
    float inv = 1.0f / pd;
    if (lane == j) {
#pragma unroll
      for (int k = j + 1; k < KD; k++) a[k] *= inv;
      b *= inv;
    }
    float f = (lane == j) ? 0.0f : a[j];
#pragma unroll
    for (int k = j + 1; k < KD; k++) {
      float pk = __shfl_sync(0xffffffffu, a[k], j);
      a[k] = fmaf(-f, pk, a[k]);
    }
    float pb = __shfl_sync(0xffffffffu, b, j);
    b = fmaf(-f, pb, b);
  }
  g_v[gw * KD + lane] = b;  // v, row-major [n][k]
}

// ---------------------------------------------------------------------------
// Kernel B: weighted moments. grid = (32 m-groups, 8 n-chunks), 256 thr/block.
// Warp w handles m = mg*8+w over its 512-n chunk. Lane owns a 4(k) x 8(l) tile
// of S in registers: per n -> 3x LDS.128 + 1 broadcast w + 4 MUL + 32 FMA.
// v tile (32n x 32k) staged to shared once per block, reused by all 8 warps.
// ---------------------------------------------------------------------------
__global__ void __launch_bounds__(256) moments_kernel(const float* __restrict__ W) {
  __shared__ __align__(16) float vt[TILE * KD];  // [n][k]
  __shared__ float wt[TILE * 8];                 // [n][m_in_group]

  int t    = threadIdx.x;
  int wid  = t >> 5;
  int lane = t & 31;
  int mg   = blockIdx.x;   // 0..31
  int c    = blockIdx.y;   // 0..7
  int m    = mg * 8 + wid;

  int kq = lane >> 2, lq = lane & 3;
  int kb = 4 * kq, lb = 8 * lq;

  float acc[4][8];
#pragma unroll
  for (int i = 0; i < 4; i++)
#pragma unroll
    for (int j = 0; j < 8; j++) acc[i][j] = 0.0f;
  float s_acc = 0.0f, Z = 0.0f, cnt = 0.0f;

  int n0 = c * CHUNK;
  int wn = t >> 3, wm = t & 7;  // w-tile loader coords (32n x 8m)

  // prefetch tile 0
  float4 vpre = *reinterpret_cast<const float4*>(&g_v[n0 * KD + 4 * t]);
  float  wpre = W[(size_t)(n0 + wn) * M_CL + mg * 8 + wm];

  const int NT = CHUNK / TILE;  // 16
  for (int nt = 0; nt < NT; nt++) {
    *reinterpret_cast<float4*>(&vt[4 * t]) = vpre;
    wt[wn * 8 + wm] = (wpre >= W_EPS) ? wpre : 0.0f;
    __syncthreads();
    if (nt + 1 < NT) {
      int nn = n0 + (nt + 1) * TILE;
      vpre = *reinterpret_cast<const float4*>(&g_v[nn * KD + 4 * t]);
      wpre = W[(size_t)(nn + wn) * M_CL + mg * 8 + wm];
    }
#pragma unroll 4
    for (int n = 0; n < TILE; n++) {
      float w = wt[n * 8 + wid];                 // broadcast
      const float* vr = &vt[n * KD];
      float4 vk = *reinterpret_cast<const float4*>(vr + kb);
      float4 va = *reinterpret_cast<const float4*>(vr + lb);
      float4 vb = *reinterpret_cast<const float4*>(vr + lb + 4);
      float  sv = vr[lane];
      float t0 = w * vk.x, t1 = w * vk.y, t2 = w * vk.z, t3 = w * vk.w;
      float vl[8] = {va.x, va.y, va.z, va.w, vb.x, vb.y, vb.z, vb.w};
#pragma unroll
      for (int j = 0; j < 8; j++) {
        acc[0][j] = fmaf(t0, vl[j], acc[0][j]);
        acc[1][j] = fmaf(t1, vl[j], acc[1][j]);
        acc[2][j] = fmaf(t2, vl[j], acc[2][j]);
        acc[3][j] = fmaf(t3, vl[j], acc[3][j]);
      }
      s_acc = fmaf(w, sv, s_acc);
      Z += w;
      cnt += (w > 0.0f) ? 1.0f : 0.0f;
    }
    __syncthreads();
  }

  float* p = g_part + (size_t)(m * SPLIT + c) * PSTRIDE;
#pragma unroll
  for (int i = 0; i < 4; i++) {
    float4 o0 = make_float4(acc[i][0], acc[i][1], acc[i][2], acc[i][3]);
    float4 o1 = make_float4(acc[i][4], acc[i][5], acc[i][6], acc[i][7]);
    *reinterpret_cast<float4*>(p + (kb + i) * KD + lb)     = o0;
    *reinterpret_cast<float4*>(p + (kb + i) * KD + lb + 4) = o1;
  }
  p[1024 + lane] = s_acc;
  if (lane == 0) { p[1056] = Z; p[1057] = cnt; }
}

// ---------------------------------------------------------------------------
// Kernel C: per-m finalize. Reduce 8 chunk partials; G = Omega^2 on the fly;
// psi = tr(G S)/Z - ||Omega s||^2 / Z^2, zeroed when count < 2.
// ---------------------------------------------------------------------------
__global__ void __launch_bounds__(256) finalize_kernel(const float* __restrict__ Omega,
                                                       float* __restrict__ out) {
  __shared__ float sS[1024];
  __shared__ float sO[1024];
  __shared__ float ssv[KD];
  __shared__ float red[256];
  __shared__ float s_trGS, s_Z, s_cnt;

  int m = blockIdx.x, t = threadIdx.x;
  const float* pb = g_part + (size_t)m * SPLIT * PSTRIDE;

  for (int e = t; e < 1024; e += 256) {
    float a = 0.0f;
#pragma unroll
    for (int c2 = 0; c2 < SPLIT; c2++) a += pb[c2 * PSTRIDE + e];
    sS[e] = a;
  }
  if (t < KD) {
    float a = 0.0f;
#pragma unroll
    for (int c2 = 0; c2 < SPLIT; c2++) a += pb[c2 * PSTRIDE + 1024 + t];
    ssv[t] = a;
  }
  if (t == 0) {
    float z = 0.0f, cn = 0.0f;
#pragma unroll
    for (int c2 = 0; c2 < SPLIT; c2++) { z += pb[c2 * PSTRIDE + 1056]; cn += pb[c2 * PSTRIDE + 1057]; }
    s_Z = z; s_cnt = cn;
  }
  for (int e = t; e < 1024; e += 256) sO[e] = Omega[(size_t)m * 1024 + e];
  __syncthreads();

  float partial = 0.0f;
  for (int e = t; e < 1024; e += 256) {
    int k = e >> 5, l = e & 31;
    float g = 0.0f;
#pragma unroll
    for (int q = 0; q < KD; q++) g = fmaf(sO[k * KD + q], sO[q * KD + l], g);
    partial = fmaf(g, sS[e], partial);
  }
  red[t] = partial;
  __syncthreads();
  for (int s = 128; s > 0; s >>= 1) { if (t < s) red[t] += red[t + s]; __syncthreads(); }
  if (t == 0) s_trGS = red[0];
  __syncthreads();

  float up = 0.0f;
  if (t < KD) {
    float u = 0.0f;
#pragma unroll
    for (int q = 0; q < KD; q++) u = fmaf(sO[t * KD + q], ssv[q], u);
    up = u * u;
  }
  red[t] = up;
  __syncthreads();
  for (int s = 128; s > 0; s >>= 1) { if (t < s) red[t] += red[t + s]; __syncthreads(); }

  if (t == 0) {
    float Z   = fmaxf(s_Z, 1e-30f);
    float psi = s_trGS / Z - red[0] / (Z * Z);
    out[m] = (s_cnt >= 1.5f) ? psi : 0.0f;
  }
}

// ---------------------------------------------------------------------------
extern "C" void kernel_launch(void* const* d_in, const int* in_sizes, int n_in,
                              void* d_out, int out_size) {
  const float* W            = (const float*)d_in[0];  // (N, M)
  const float* mu_s         = (const float*)d_in[1];  // (N, K)
  const float* omega_child  = (const float*)d_in[2];  // (N, K, K)
  const float* omega_parent = (const float*)d_in[3];  // (M, K, K)
  float* out = (float*)d_out;                         // (M,)

  solve_kernel<<<N_AG / 8, 256>>>(omega_child, mu_s);
  dim3 gB(M_CL / 8, SPLIT);
  moments_kernel<<<gB, 256>>>(W);
  finalize_kernel<<<M_CL, 256>>>(omega_parent, out);
}